// round 6
// baseline (speedup 1.0000x reference)
#include <cuda_runtime.h>

#define TB      64      // batch rows per CTA
#define RPAD    66      // row stride (floats), even => aligned float2 row-pairs
#define NTHREADS 256
#define OMEGA_F 30.0f

// ---------- f32x2 packed math (Blackwell FFMA2) ----------
static __device__ __forceinline__ unsigned long long pack2(float a, float b) {
    unsigned long long r;
    asm("mov.b64 %0, {%1, %2};" : "=l"(r) : "f"(a), "f"(b));
    return r;
}
static __device__ __forceinline__ void unpack2(unsigned long long v, float &a, float &b) {
    asm("mov.b64 {%0, %1}, %2;" : "=f"(a), "=f"(b) : "l"(v));
}
static __device__ __forceinline__ unsigned long long fma2(unsigned long long a,
                                                          unsigned long long b,
                                                          unsigned long long c) {
    unsigned long long d;
    asm("fma.rn.f32x2 %0, %1, %2, %3;" : "=l"(d) : "l"(a), "l"(b), "l"(c));
    return d;
}

// ---------------------------------------------------------------------------
// Reformatted weight store: for each layer, layout [K/2][N] of ulonglong2
//   elem(k2, n) = { pack2(W[n][2k2],W[n][2k2]), pack2(W[n][2k2+1],W[n][2k2+1]) }
// Total 528,640 elements = 8.46 MB (L2-resident).
// ---------------------------------------------------------------------------
#define OFF_ENC1 0          //  64x128 -> 4096
#define OFF_ENC2 4096       // 128x256 -> 16384
#define OFF_RES1 20480      // 256x128 -> 16384
#define OFF_RES2 36864      // 128x128 -> 8192
#define OFF_RES3 45056      // 128x256 -> 16384
#define OFF_POL1 61440      //   4x128 -> 256
#define OFF_POL2 61696      // 128x128 -> 8192
#define OFF_EXP1 69888      // 7x 256x256 -> 229376
#define OFF_EXP2 299264     // 7x 256x256 -> 229376
#define WT_TOTAL 528640

__device__ ulonglong2 g_wt[WT_TOTAL];

// Reformat kernel: src is [NB][N][K] row-major; dst region is [NB][K/2][N].
__global__ void reformat_w(const float* __restrict__ src, int dst_off,
                           int N, int K, int NB)
{
    int idx = blockIdx.x * blockDim.x + threadIdx.x;
    int K2 = K / 2;
    int total = NB * K2 * N;
    if (idx >= total) return;
    int n  = idx % N;
    int t  = idx / N;
    int k2 = t % K2;
    int nb = t / K2;
    const float* s = src + ((long long)(nb * N + n)) * K + 2 * k2;
    float w0 = s[0], w1 = s[1];
    ulonglong2 v;
    v.x = pack2(w0, w0);
    v.y = pack2(w1, w1);
    g_wt[dst_off + idx] = v;
}

// Shared memory layout (floats)
#define SM_BUFE 0
#define SM_BUFT (256 * RPAD)
#define SM_BUFU (2 * 256 * RPAD)
#define SM_XS   (3 * 256 * RPAD)
#define SM_PROB (SM_XS + 4 * RPAD)
#define SM_YACC (SM_PROB + 7 * TB)
#define SM_SCR  (SM_YACC + TB)
#define SM_TOTAL (SM_SCR + 4 * TB)

// ---------------------------------------------------------------------------
// Fused GEMM layer, direct-LDG weights (pre-transposed + pre-duplicated).
//   in  : smem activations, [K][RPAD] feature-major
//   Wt  : g_wt region, [K/2][N] ulonglong2 (dup'd pairs)
//   out : smem activations, [N][RPAD]
//   ACT : 0 = sin(OMEGA*z), 1 = relu(z), 2 = relu(z + res)
// Thread tile: 8 rows (4 row-pairs, warp-owned) x NCOL cols (n = lane + 32j).
// Per 2 k-steps: 8 LDS.64 broadcast (a) + NCOL LDG.128 (w) + 8*NCOL FFMA2.
// No barriers inside the k-loop; one __syncthreads at layer end.
// PD = k-pair software-pipeline depth (K/2 % PD must be 0).
// ---------------------------------------------------------------------------
template <int K, int NCOL, int ACT, int PD>
static __device__ __forceinline__ void gemm_g(
    const float* __restrict__ in, const ulonglong2* __restrict__ Wt,
    const float* __restrict__ bias, float* __restrict__ out,
    const float* __restrict__ res)
{
    constexpr int N  = NCOL * 32;
    constexpr int K2 = K / 2;
    static_assert(K2 % PD == 0, "K2 % PD");

    const int tid  = threadIdx.x;
    const int lane = tid & 31;
    const int warp = tid >> 5;
    const int r0   = warp * 8;

    unsigned long long acc[4][NCOL];
#pragma unroll
    for (int i = 0; i < 4; i++)
#pragma unroll
        for (int j = 0; j < NCOL; j++) acc[i][j] = 0ull;

    const ulonglong2* Wp = Wt + lane;

    // prologue: fill PD k-pair stages
    ulonglong2 wreg[PD][NCOL];
#pragma unroll
    for (int d = 0; d < PD; d++)
#pragma unroll
        for (int j = 0; j < NCOL; j++)
            wreg[d][j] = __ldg(Wp + d * N + 32 * j);

    for (int k2 = 0; k2 < K2; k2 += PD) {
#pragma unroll
        for (int d = 0; d < PD; d++) {
            const int k = 2 * (k2 + d);
            const float* a0p = in + k * RPAD + r0;
            const float* a1p = a0p + RPAD;
            unsigned long long a0[4], a1[4];
#pragma unroll
            for (int i = 0; i < 4; i++) {         // broadcast LDS.64 row-pairs
                a0[i] = *(const unsigned long long*)(a0p + 2 * i);
                a1[i] = *(const unsigned long long*)(a1p + 2 * i);
            }
#pragma unroll
            for (int j = 0; j < NCOL; j++) {
                unsigned long long w0 = wreg[d][j].x;
                unsigned long long w1 = wreg[d][j].y;
#pragma unroll
                for (int i = 0; i < 4; i++) acc[i][j] = fma2(a0[i], w0, acc[i][j]);
#pragma unroll
                for (int i = 0; i < 4; i++) acc[i][j] = fma2(a1[i], w1, acc[i][j]);
            }
            // prefetch stage d for iteration k2+PD
            if (k2 + d + PD < K2) {
#pragma unroll
                for (int j = 0; j < NCOL; j++)
                    wreg[d][j] = __ldg(Wp + (k2 + d + PD) * N + 32 * j);
            }
        }
    }

    // epilogue: bias + activation, store transposed [n][row] as float2
#pragma unroll
    for (int j = 0; j < NCOL; j++) {
        int n = lane + 32 * j;
        float b = __ldg(bias + n);
#pragma unroll
        for (int i = 0; i < 4; i++) {
            float z0, z1;
            unpack2(acc[i][j], z0, z1);
            z0 += b; z1 += b;
            if (ACT == 0) {
                z0 = __sinf(OMEGA_F * z0);
                z1 = __sinf(OMEGA_F * z1);
            } else if (ACT == 1) {
                z0 = fmaxf(z0, 0.0f);
                z1 = fmaxf(z1, 0.0f);
            } else {
                float2 rv = *(const float2*)(res + n * RPAD + r0 + 2 * i);
                z0 = fmaxf(z0 + rv.x, 0.0f);
                z1 = fmaxf(z1 + rv.y, 0.0f);
            }
            *(float2*)(out + n * RPAD + r0 + 2 * i) = make_float2(z0, z1);
        }
    }
    __syncthreads();
}

// ---------------------------------------------------------------------------
__global__ void __launch_bounds__(NTHREADS, 1)
moe_inr_kernel(
    const float* __restrict__ x,
    const float* __restrict__ enc_s1_b, const float* __restrict__ enc_s2_b,
    const float* __restrict__ res_fc1_b, const float* __restrict__ res_fc2_b,
    const float* __restrict__ res_fc3_b,
    const float* __restrict__ pol_s1_b, const float* __restrict__ pol_s2_b,
    const float* __restrict__ gate_w, const float* __restrict__ gate_b,
    const float* __restrict__ exp_s1_b, const float* __restrict__ exp_s2_b,
    const float* __restrict__ exp_fin_w, const float* __restrict__ exp_fin_b,
    float* __restrict__ out)
{
    extern __shared__ float smem[];
    float* bufE  = smem + SM_BUFE;
    float* bufT  = smem + SM_BUFT;
    float* bufU  = smem + SM_BUFU;
    float* xs    = smem + SM_XS;
    float* probs = smem + SM_PROB;
    float* yacc  = smem + SM_YACC;
    float* scr   = smem + SM_SCR;

    const int tid = threadIdx.x;
    const long long rowbase = (long long)blockIdx.x * TB;

    // ---- load x tile: [4][RPAD] feature-major (256 = 64*4 exactly) ----
    {
        int r = tid >> 2, d = tid & 3;
        xs[d * RPAD + r] = x[(rowbase + r) * 4 + d];
    }
    __syncthreads();

    // ---- positional encoding -> bufT rows [0,64): col = d*16+f; f<8 sin else cos ----
    for (int idx = tid; idx < 64 * TB; idx += NTHREADS) {
        int r = idx & (TB - 1), c = idx / TB;
        int d = c >> 4, f = c & 15;
        float freq = exp2f((float)(f & 7)) * 3.14159265358979323846f;
        float ang  = xs[d * RPAD + r] * freq;
        bufT[c * RPAD + r] = (f < 8) ? sinf(ang) : cosf(ang);
    }
    __syncthreads();

    // ---- encoder ----
    gemm_g< 64, 4, 0, 2>(bufT, g_wt + OFF_ENC1, enc_s1_b,  bufU, nullptr); // sin ->128
    gemm_g<128, 8, 0, 2>(bufU, g_wt + OFF_ENC2, enc_s2_b,  bufE, nullptr); // sin -> h 256
    gemm_g<256, 4, 1, 2>(bufE, g_wt + OFF_RES1, res_fc1_b, bufT, nullptr); // relu ->128
    gemm_g<128, 4, 1, 2>(bufT, g_wt + OFF_RES2, res_fc2_b, bufU, nullptr); // relu ->128
    gemm_g<128, 8, 2, 2>(bufU, g_wt + OFF_RES3, res_fc3_b, bufE, bufE);    // relu(r+h)

    // ---- policy ----
    gemm_g<  4, 4, 0, 2>(xs,   g_wt + OFF_POL1, pol_s1_b,  bufT, nullptr); // sin ->128
    gemm_g<128, 4, 0, 2>(bufT, g_wt + OFF_POL2, pol_s2_b,  bufU, nullptr); // sin -> pf

    // ---- gate: logits over concat(enc_feat[256], pf[128]) ----
    float* gbuf = bufT;   // dead (pol_s2 consumed it); 16896 floats available
    for (int idx = tid; idx < 7 * 384; idx += NTHREADS) gbuf[idx] = gate_w[idx];
    __syncthreads();
    for (int idx = tid; idx < 7 * TB; idx += NTHREADS) {
        int r = idx & (TB - 1), c = idx / TB;
        const float* gw = gbuf + c * 384;
        float s = __ldg(gate_b + c);
        for (int k = 0; k < 256; k++) s += bufE[k * RPAD + r] * gw[k];
        for (int k = 0; k < 128; k++) s += bufU[k * RPAD + r] * gw[256 + k];
        probs[c * TB + r] = s;
    }
    __syncthreads();
    if (tid < TB) {
        int r = tid;
        float m = -1e30f;
        for (int c = 0; c < 7; c++) m = fmaxf(m, probs[c * TB + r]);
        float s = 0.0f, e[7];
        for (int c = 0; c < 7; c++) { e[c] = __expf(probs[c * TB + r] - m); s += e[c]; }
        float inv = 1.0f / s;
        for (int c = 0; c < 7; c++) probs[c * TB + r] = e[c] * inv;
        yacc[r] = 0.0f;
    }
    __syncthreads();

    // ---- experts ----
    for (int e = 0; e < 7; e++) {
        gemm_g<256, 8, 0, 2>(bufE, g_wt + OFF_EXP1 + e * 32768,
                             exp_s1_b + e * 256, bufT, nullptr);
        gemm_g<256, 8, 0, 2>(bufT, g_wt + OFF_EXP2 + e * 32768,
                             exp_s2_b + e * 256, bufU, nullptr);
        // final linear [256]->1, 4-way split reduction per row
        {
            int part = tid >> 6, r = tid & 63;
            const float* Wf = exp_fin_w + e * 256;
            float s = 0.0f;
            int k0 = part * 64;
            for (int k = k0; k < k0 + 64; k++) s += bufU[k * RPAD + r] * __ldg(Wf + k);
            scr[part * TB + r] = s;
        }
        __syncthreads();
        if (tid < TB) {
            int r = tid;
            float pred = scr[r] + scr[TB + r] + scr[2 * TB + r] + scr[3 * TB + r]
                       + __ldg(exp_fin_b + e);
            yacc[r] += probs[e * TB + r] * pred;
        }
        __syncthreads();
    }

    if (tid < TB) out[rowbase + tid] = yacc[tid];
}

// ---------------------------------------------------------------------------
static inline void launch_reformat(const float* src, int dst_off, int N, int K, int NB)
{
    int total = NB * (K / 2) * N;
    reformat_w<<<(total + 255) / 256, 256>>>(src, dst_off, N, K, NB);
}

extern "C" void kernel_launch(void* const* d_in, const int* in_sizes, int n_in,
                              void* d_out, int out_size)
{
    const float* x         = (const float*)d_in[0];
    const float* enc_s1_w  = (const float*)d_in[1];
    const float* enc_s1_b  = (const float*)d_in[2];
    const float* enc_s2_w  = (const float*)d_in[3];
    const float* enc_s2_b  = (const float*)d_in[4];
    const float* res_fc1_w = (const float*)d_in[5];
    const float* res_fc1_b = (const float*)d_in[6];
    const float* res_fc2_w = (const float*)d_in[7];
    const float* res_fc2_b = (const float*)d_in[8];
    const float* res_fc3_w = (const float*)d_in[9];
    const float* res_fc3_b = (const float*)d_in[10];
    const float* pol_s1_w  = (const float*)d_in[11];
    const float* pol_s1_b  = (const float*)d_in[12];
    const float* pol_s2_w  = (const float*)d_in[13];
    const float* pol_s2_b  = (const float*)d_in[14];
    const float* gate_w    = (const float*)d_in[15];
    const float* gate_b    = (const float*)d_in[16];
    const float* exp_s1_w  = (const float*)d_in[17];
    const float* exp_s1_b  = (const float*)d_in[18];
    const float* exp_s2_w  = (const float*)d_in[19];
    const float* exp_s2_b  = (const float*)d_in[20];
    const float* exp_fin_w = (const float*)d_in[21];
    const float* exp_fin_b = (const float*)d_in[22];

    // reformat all GEMM weights into g_wt (cheap; runs every launch, deterministic)
    launch_reformat(enc_s1_w,  OFF_ENC1, 128,  64, 1);
    launch_reformat(enc_s2_w,  OFF_ENC2, 256, 128, 1);
    launch_reformat(res_fc1_w, OFF_RES1, 128, 256, 1);
    launch_reformat(res_fc2_w, OFF_RES2, 128, 128, 1);
    launch_reformat(res_fc3_w, OFF_RES3, 256, 128, 1);
    launch_reformat(pol_s1_w,  OFF_POL1, 128,   4, 1);
    launch_reformat(pol_s2_w,  OFF_POL2, 128, 128, 1);
    launch_reformat(exp_s1_w,  OFF_EXP1, 256, 256, 7);
    launch_reformat(exp_s2_w,  OFF_EXP2, 256, 256, 7);

    int B = in_sizes[0] / 4;
    int grid = B / TB;
    size_t shmem = (size_t)SM_TOTAL * sizeof(float);

    cudaFuncSetAttribute(moe_inr_kernel,
                         cudaFuncAttributeMaxDynamicSharedMemorySize, (int)shmem);

    moe_inr_kernel<<<grid, NTHREADS, shmem>>>(
        x, enc_s1_b, enc_s2_b,
        res_fc1_b, res_fc2_b, res_fc3_b,
        pol_s1_b, pol_s2_b, gate_w, gate_b,
        exp_s1_b, exp_s2_b, exp_fin_w, exp_fin_b,
        (float*)d_out);
}

// round 7
// speedup vs baseline: 1.0008x; 1.0008x over previous
#include <cuda_runtime.h>

#define TB      64      // batch rows per CTA
#define RPAD    66      // row stride (floats), even => aligned float2 row-pairs
#define NTHREADS 256
#define OMEGA_F 30.0f

// ---------- f32x2 packed math (Blackwell FFMA2) ----------
static __device__ __forceinline__ unsigned long long pack2(float a, float b) {
    unsigned long long r;
    asm("mov.b64 %0, {%1, %2};" : "=l"(r) : "f"(a), "f"(b));
    return r;
}
static __device__ __forceinline__ void unpack2(unsigned long long v, float &a, float &b) {
    asm("mov.b64 {%0, %1}, %2;" : "=f"(a), "=f"(b) : "l"(v));
}
static __device__ __forceinline__ unsigned long long fma2(unsigned long long a,
                                                          unsigned long long b,
                                                          unsigned long long c) {
    unsigned long long d;
    asm("fma.rn.f32x2 %0, %1, %2, %3;" : "=l"(d) : "l"(a), "l"(b), "l"(c));
    return d;
}

// ---------------------------------------------------------------------------
// Reformatted weight store: for each layer, layout [K/2][N] of ulonglong2
//   elem(k2, n) = { pack2(W[n][2k2],W[n][2k2]), pack2(W[n][2k2+1],W[n][2k2+1]) }
// Total 528,640 elements = 8.46 MB (L2-resident).
// ---------------------------------------------------------------------------
#define OFF_ENC1 0          //  64x128 -> 4096
#define OFF_ENC2 4096       // 128x256 -> 16384
#define OFF_RES1 20480      // 256x128 -> 16384
#define OFF_RES2 36864      // 128x128 -> 8192
#define OFF_RES3 45056      // 128x256 -> 16384
#define OFF_POL1 61440      //   4x128 -> 256
#define OFF_POL2 61696      // 128x128 -> 8192
#define OFF_EXP1 69888      // 7x 256x256 -> 229376
#define OFF_EXP2 299264     // 7x 256x256 -> 229376
#define WT_TOTAL 528640

__device__ ulonglong2 g_wt[WT_TOTAL];

// Reformat kernel: src is [NB][N][K] row-major; dst region is [NB][K/2][N].
__global__ void reformat_w(const float* __restrict__ src, int dst_off,
                           int N, int K, int NB)
{
    int idx = blockIdx.x * blockDim.x + threadIdx.x;
    int K2 = K / 2;
    int total = NB * K2 * N;
    if (idx >= total) return;
    int n  = idx % N;
    int t  = idx / N;
    int k2 = t % K2;
    int nb = t / K2;
    const float* s = src + ((long long)(nb * N + n)) * K + 2 * k2;
    float w0 = s[0], w1 = s[1];
    ulonglong2 v;
    v.x = pack2(w0, w0);
    v.y = pack2(w1, w1);
    g_wt[dst_off + idx] = v;
}

// Shared memory layout (floats)
#define SM_BUFE 0
#define SM_BUFT (256 * RPAD)
#define SM_BUFU (2 * 256 * RPAD)
#define SM_XS   (3 * 256 * RPAD)
#define SM_PROB (SM_XS + 4 * RPAD)
#define SM_YACC (SM_PROB + 7 * TB)
#define SM_SCR  (SM_YACC + TB)
#define SM_TOTAL (SM_SCR + 4 * TB)

// ---------------------------------------------------------------------------
// Fused GEMM layer, direct-LDG weights (pre-transposed + pre-duplicated).
//   in  : smem activations, [K][RPAD] feature-major
//   Wt  : g_wt region, [K/2][N] ulonglong2 (dup'd pairs)
//   out : smem activations, [N][RPAD]
//   ACT : 0 = sin(OMEGA*z), 1 = relu(z), 2 = relu(z + res)
// Thread tile: 8 rows (4 row-pairs, warp-owned) x NCOL cols (n = lane + 32j).
// Per 2 k-steps: 8 LDS.64 broadcast (a) + NCOL LDG.128 (w) + 8*NCOL FFMA2.
// No barriers inside the k-loop; one __syncthreads at layer end.
// PD = k-pair software-pipeline depth (K/2 % PD must be 0).
// ---------------------------------------------------------------------------
template <int K, int NCOL, int ACT, int PD>
static __device__ __forceinline__ void gemm_g(
    const float* __restrict__ in, const ulonglong2* __restrict__ Wt,
    const float* __restrict__ bias, float* __restrict__ out,
    const float* __restrict__ res)
{
    constexpr int N  = NCOL * 32;
    constexpr int K2 = K / 2;
    static_assert(K2 % PD == 0, "K2 % PD");

    const int tid  = threadIdx.x;
    const int lane = tid & 31;
    const int warp = tid >> 5;
    const int r0   = warp * 8;

    unsigned long long acc[4][NCOL];
#pragma unroll
    for (int i = 0; i < 4; i++)
#pragma unroll
        for (int j = 0; j < NCOL; j++) acc[i][j] = 0ull;

    const ulonglong2* Wp = Wt + lane;

    // prologue: fill PD k-pair stages
    ulonglong2 wreg[PD][NCOL];
#pragma unroll
    for (int d = 0; d < PD; d++)
#pragma unroll
        for (int j = 0; j < NCOL; j++)
            wreg[d][j] = __ldg(Wp + d * N + 32 * j);

    for (int k2 = 0; k2 < K2; k2 += PD) {
#pragma unroll
        for (int d = 0; d < PD; d++) {
            const int k = 2 * (k2 + d);
            const float* a0p = in + k * RPAD + r0;
            const float* a1p = a0p + RPAD;
            unsigned long long a0[4], a1[4];
#pragma unroll
            for (int i = 0; i < 4; i++) {         // broadcast LDS.64 row-pairs
                a0[i] = *(const unsigned long long*)(a0p + 2 * i);
                a1[i] = *(const unsigned long long*)(a1p + 2 * i);
            }
#pragma unroll
            for (int j = 0; j < NCOL; j++) {
                unsigned long long w0 = wreg[d][j].x;
                unsigned long long w1 = wreg[d][j].y;
#pragma unroll
                for (int i = 0; i < 4; i++) acc[i][j] = fma2(a0[i], w0, acc[i][j]);
#pragma unroll
                for (int i = 0; i < 4; i++) acc[i][j] = fma2(a1[i], w1, acc[i][j]);
            }
            // prefetch stage d for iteration k2+PD
            if (k2 + d + PD < K2) {
#pragma unroll
                for (int j = 0; j < NCOL; j++)
                    wreg[d][j] = __ldg(Wp + (k2 + d + PD) * N + 32 * j);
            }
        }
    }

    // epilogue: bias + activation, store transposed [n][row] as float2
#pragma unroll
    for (int j = 0; j < NCOL; j++) {
        int n = lane + 32 * j;
        float b = __ldg(bias + n);
#pragma unroll
        for (int i = 0; i < 4; i++) {
            float z0, z1;
            unpack2(acc[i][j], z0, z1);
            z0 += b; z1 += b;
            if (ACT == 0) {
                z0 = __sinf(OMEGA_F * z0);
                z1 = __sinf(OMEGA_F * z1);
            } else if (ACT == 1) {
                z0 = fmaxf(z0, 0.0f);
                z1 = fmaxf(z1, 0.0f);
            } else {
                float2 rv = *(const float2*)(res + n * RPAD + r0 + 2 * i);
                z0 = fmaxf(z0 + rv.x, 0.0f);
                z1 = fmaxf(z1 + rv.y, 0.0f);
            }
            *(float2*)(out + n * RPAD + r0 + 2 * i) = make_float2(z0, z1);
        }
    }
    __syncthreads();
}

// ---------------------------------------------------------------------------
__global__ void __launch_bounds__(NTHREADS, 1)
moe_inr_kernel(
    const float* __restrict__ x,
    const float* __restrict__ enc_s1_b, const float* __restrict__ enc_s2_b,
    const float* __restrict__ res_fc1_b, const float* __restrict__ res_fc2_b,
    const float* __restrict__ res_fc3_b,
    const float* __restrict__ pol_s1_b, const float* __restrict__ pol_s2_b,
    const float* __restrict__ gate_w, const float* __restrict__ gate_b,
    const float* __restrict__ exp_s1_b, const float* __restrict__ exp_s2_b,
    const float* __restrict__ exp_fin_w, const float* __restrict__ exp_fin_b,
    float* __restrict__ out)
{
    extern __shared__ float smem[];
    float* bufE  = smem + SM_BUFE;
    float* bufT  = smem + SM_BUFT;
    float* bufU  = smem + SM_BUFU;
    float* xs    = smem + SM_XS;
    float* probs = smem + SM_PROB;
    float* yacc  = smem + SM_YACC;
    float* scr   = smem + SM_SCR;

    const int tid = threadIdx.x;
    const long long rowbase = (long long)blockIdx.x * TB;

    // ---- load x tile: [4][RPAD] feature-major (256 = 64*4 exactly) ----
    {
        int r = tid >> 2, d = tid & 3;
        xs[d * RPAD + r] = x[(rowbase + r) * 4 + d];
    }
    __syncthreads();

    // ---- positional encoding -> bufT rows [0,64): col = d*16+f; f<8 sin else cos ----
    for (int idx = tid; idx < 64 * TB; idx += NTHREADS) {
        int r = idx & (TB - 1), c = idx / TB;
        int d = c >> 4, f = c & 15;
        float freq = exp2f((float)(f & 7)) * 3.14159265358979323846f;
        float ang  = xs[d * RPAD + r] * freq;
        bufT[c * RPAD + r] = (f < 8) ? sinf(ang) : cosf(ang);
    }
    __syncthreads();

    // ---- encoder ----
    gemm_g< 64, 4, 0, 2>(bufT, g_wt + OFF_ENC1, enc_s1_b,  bufU, nullptr); // sin ->128
    gemm_g<128, 8, 0, 2>(bufU, g_wt + OFF_ENC2, enc_s2_b,  bufE, nullptr); // sin -> h 256
    gemm_g<256, 4, 1, 2>(bufE, g_wt + OFF_RES1, res_fc1_b, bufT, nullptr); // relu ->128
    gemm_g<128, 4, 1, 2>(bufT, g_wt + OFF_RES2, res_fc2_b, bufU, nullptr); // relu ->128
    gemm_g<128, 8, 2, 2>(bufU, g_wt + OFF_RES3, res_fc3_b, bufE, bufE);    // relu(r+h)

    // ---- policy ----
    gemm_g<  4, 4, 0, 2>(xs,   g_wt + OFF_POL1, pol_s1_b,  bufT, nullptr); // sin ->128
    gemm_g<128, 4, 0, 2>(bufT, g_wt + OFF_POL2, pol_s2_b,  bufU, nullptr); // sin -> pf

    // ---- gate: logits over concat(enc_feat[256], pf[128]) ----
    float* gbuf = bufT;   // dead (pol_s2 consumed it); 16896 floats available
    for (int idx = tid; idx < 7 * 384; idx += NTHREADS) gbuf[idx] = gate_w[idx];
    __syncthreads();
    for (int idx = tid; idx < 7 * TB; idx += NTHREADS) {
        int r = idx & (TB - 1), c = idx / TB;
        const float* gw = gbuf + c * 384;
        float s = __ldg(gate_b + c);
        for (int k = 0; k < 256; k++) s += bufE[k * RPAD + r] * gw[k];
        for (int k = 0; k < 128; k++) s += bufU[k * RPAD + r] * gw[256 + k];
        probs[c * TB + r] = s;
    }
    __syncthreads();
    if (tid < TB) {
        int r = tid;
        float m = -1e30f;
        for (int c = 0; c < 7; c++) m = fmaxf(m, probs[c * TB + r]);
        float s = 0.0f, e[7];
        for (int c = 0; c < 7; c++) { e[c] = __expf(probs[c * TB + r] - m); s += e[c]; }
        float inv = 1.0f / s;
        for (int c = 0; c < 7; c++) probs[c * TB + r] = e[c] * inv;
        yacc[r] = 0.0f;
    }
    __syncthreads();

    // ---- experts ----
    for (int e = 0; e < 7; e++) {
        gemm_g<256, 8, 0, 2>(bufE, g_wt + OFF_EXP1 + e * 32768,
                             exp_s1_b + e * 256, bufT, nullptr);
        gemm_g<256, 8, 0, 2>(bufT, g_wt + OFF_EXP2 + e * 32768,
                             exp_s2_b + e * 256, bufU, nullptr);
        // final linear [256]->1, 4-way split reduction per row
        {
            int part = tid >> 6, r = tid & 63;
            const float* Wf = exp_fin_w + e * 256;
            float s = 0.0f;
            int k0 = part * 64;
            for (int k = k0; k < k0 + 64; k++) s += bufU[k * RPAD + r] * __ldg(Wf + k);
            scr[part * TB + r] = s;
        }
        __syncthreads();
        if (tid < TB) {
            int r = tid;
            float pred = scr[r] + scr[TB + r] + scr[2 * TB + r] + scr[3 * TB + r]
                       + __ldg(exp_fin_b + e);
            yacc[r] += probs[e * TB + r] * pred;
        }
        __syncthreads();
    }

    if (tid < TB) out[rowbase + tid] = yacc[tid];
}

// ---------------------------------------------------------------------------
static inline void launch_reformat(const float* src, int dst_off, int N, int K, int NB)
{
    int total = NB * (K / 2) * N;
    reformat_w<<<(total + 255) / 256, 256>>>(src, dst_off, N, K, NB);
}

extern "C" void kernel_launch(void* const* d_in, const int* in_sizes, int n_in,
                              void* d_out, int out_size)
{
    const float* x         = (const float*)d_in[0];
    const float* enc_s1_w  = (const float*)d_in[1];
    const float* enc_s1_b  = (const float*)d_in[2];
    const float* enc_s2_w  = (const float*)d_in[3];
    const float* enc_s2_b  = (const float*)d_in[4];
    const float* res_fc1_w = (const float*)d_in[5];
    const float* res_fc1_b = (const float*)d_in[6];
    const float* res_fc2_w = (const float*)d_in[7];
    const float* res_fc2_b = (const float*)d_in[8];
    const float* res_fc3_w = (const float*)d_in[9];
    const float* res_fc3_b = (const float*)d_in[10];
    const float* pol_s1_w  = (const float*)d_in[11];
    const float* pol_s1_b  = (const float*)d_in[12];
    const float* pol_s2_w  = (const float*)d_in[13];
    const float* pol_s2_b  = (const float*)d_in[14];
    const float* gate_w    = (const float*)d_in[15];
    const float* gate_b    = (const float*)d_in[16];
    const float* exp_s1_w  = (const float*)d_in[17];
    const float* exp_s1_b  = (const float*)d_in[18];
    const float* exp_s2_w  = (const float*)d_in[19];
    const float* exp_s2_b  = (const float*)d_in[20];
    const float* exp_fin_w = (const float*)d_in[21];
    const float* exp_fin_b = (const float*)d_in[22];

    // reformat all GEMM weights into g_wt (cheap; runs every launch, deterministic)
    launch_reformat(enc_s1_w,  OFF_ENC1, 128,  64, 1);
    launch_reformat(enc_s2_w,  OFF_ENC2, 256, 128, 1);
    launch_reformat(res_fc1_w, OFF_RES1, 128, 256, 1);
    launch_reformat(res_fc2_w, OFF_RES2, 128, 128, 1);
    launch_reformat(res_fc3_w, OFF_RES3, 256, 128, 1);
    launch_reformat(pol_s1_w,  OFF_POL1, 128,   4, 1);
    launch_reformat(pol_s2_w,  OFF_POL2, 128, 128, 1);
    launch_reformat(exp_s1_w,  OFF_EXP1, 256, 256, 7);
    launch_reformat(exp_s2_w,  OFF_EXP2, 256, 256, 7);

    int B = in_sizes[0] / 4;
    int grid = B / TB;
    size_t shmem = (size_t)SM_TOTAL * sizeof(float);

    cudaFuncSetAttribute(moe_inr_kernel,
                         cudaFuncAttributeMaxDynamicSharedMemorySize, (int)shmem);

    moe_inr_kernel<<<grid, NTHREADS, shmem>>>(
        x, enc_s1_b, enc_s2_b,
        res_fc1_b, res_fc2_b, res_fc3_b,
        pol_s1_b, pol_s2_b, gate_w, gate_b,
        exp_s1_b, exp_s2_b, exp_fin_w, exp_fin_b,
        (float*)d_out);
}